// round 11
// baseline (speedup 1.0000x reference)
#include <cuda_runtime.h>

// DistMaps: out[b,g,r,c] = tanh(2*sqrt(min_p d2)) over 24 clicks per (b,g) group,
// d2 = ((r-pr)/5)^2 + ((c-pc)/5)^2, invalid clicks (max coords < 0) -> 1e6.
// x input (d_in[0]) is shape-only; output depends only on coords (d_in[1]).
//
// R11: R10 shape + tolerance-aware culling. The bench accepts rel_err < 1e-3;
// at culled pixels ref ~= 1.0, so writing 1.0f is valid wherever
// 1 - tanh(2*sqrt(d2)) <= 1e-4 (10x margin), i.e. d2 >= 6.25 (2*sqrt = 5,
// 1-tanh(5) = 9.1e-5). Influence radius shrinks 32px -> 12.5px, so the
// fraction of warps with zero surviving clicks rises from ~30% to ~67%,
// cutting mean issued instructions per warp ~1.9x (the binding resource:
// R9/R10 profiles showed pure issue-count limitation at ~49% efficiency).
// Interior pixels (d2 < 6.25) are still computed exactly.

namespace {

constexpr int   W         = 512;
constexpr int   P         = 24;      // clicks per group
constexpr float INV_SCALE = 0.2f;    // 1 / (NORM_RADIUS * SPATIAL_SCALE)
// 1 - tanh(2*sqrt(6.25)) = 1 - tanh(5) = 9.1e-5  << 1e-3 tolerance.
constexpr float CULL_D2   = 6.25f;

__device__ __forceinline__ float tanh_2sqrt_fast(float q) {
    float s, t;
    asm("sqrt.approx.f32 %0, %1;" : "=f"(s) : "f"(q));
    s = 2.0f * s;
    asm("tanh.approx.f32 %0, %1;" : "=f"(t) : "f"(s));
    return t;
}

__global__ __launch_bounds__(256, 6) void distmaps_kernel(
    const float* __restrict__ coords,   // [B, 48, 3] (row, col, _)
    float*       __restrict__ out)      // [B, 2, H, W]
{
    const int tid  = threadIdx.x;
    const int lane = tid & 31;
    const int bg   = blockIdx.y;                   // 0..2B-1

    const int wloc = (blockIdx.x << 3) + (tid >> 5);  // 0..511 window in group
    const int r0   = (wloc >> 2) << 2;             // window row base (4 rows)
    const int c0   = (wloc & 3) << 7;              // window col base (128 cols)

    // Lane p holds click p; test click against this warp's 4x128 window.
    float prs = 0.0f, pcs = 0.0f;
    bool  near = false;
    if (lane < P) {
        const float* cp = coords + (bg * P + lane) * 3;
        const float pr = __ldg(cp);
        const float pc = __ldg(cp + 1);
        const bool valid = fmaxf(pr, pc) >= 0.0f;      // invalid iff both < 0
        const float rr = fminf(fmaxf(pr, (float)r0), (float)(r0 + 3));
        const float cc = fminf(fmaxf(pc, (float)c0), (float)(c0 + 127));
        const float dr = (rr - pr) * INV_SCALE;
        const float dc = (cc - pc) * INV_SCALE;
        near = valid && (fmaf(dr, dr, dc * dc) < CULL_D2);
        prs = pr * INV_SCALE;
        pcs = pc * INV_SCALE;
    }
    unsigned mask = __ballot_sync(0xffffffffu, near);

    // Output index: bg<<18 | r0<<9 | c0 | lane<<2 (disjoint bit fields).
    const unsigned idx = ((unsigned)bg << 18) | ((unsigned)r0 << 9) |
                         (unsigned)(c0 | (lane << 2));
    float* obase = out + idx;

    if (mask == 0u) {
        // No click within 12.5px of this window: all pixels -> 1.0f
        // (error <= 9.1e-5, 10x inside the 1e-3 tolerance).
        const float4 ones = make_float4(1.0f, 1.0f, 1.0f, 1.0f);
#pragma unroll
        for (int i = 0; i < 4; ++i)
            *reinterpret_cast<float4*>(obase + i * W) = ones;
        return;
    }

    // Incremental coordinate setup (1 I2F + 1 FMUL + 3 FADD per axis).
    const float a0  = (float)(c0 | (lane << 2)) * INV_SCALE;
    const float a1  = a0 + INV_SCALE;
    const float a2  = a1 + INV_SCALE;
    const float a3  = a2 + INV_SCALE;
    const float rs0 = (float)r0 * INV_SCALE;
    const float rs1 = rs0 + INV_SCALE;
    const float rs2 = rs1 + INV_SCALE;
    const float rs3 = rs2 + INV_SCALE;

    float q[4][4];
#pragma unroll
    for (int i = 0; i < 4; ++i)
#pragma unroll
        for (int j = 0; j < 4; ++j) q[i][j] = CULL_D2;

    // Iterate surviving clicks (warp-uniform mask -> no divergence).
    while (mask) {
        const int p = __ffs(mask) - 1;
        mask &= mask - 1;
        const float pr = __shfl_sync(0xffffffffu, prs, p);
        const float pc = __shfl_sync(0xffffffffu, pcs, p);

        const float dc0 = a0 - pc, dc1 = a1 - pc, dc2 = a2 - pc, dc3 = a3 - pc;
        float dr, e;
        dr = rs0 - pr; e = dr * dr;
        q[0][0] = fminf(q[0][0], fmaf(dc0, dc0, e));
        q[0][1] = fminf(q[0][1], fmaf(dc1, dc1, e));
        q[0][2] = fminf(q[0][2], fmaf(dc2, dc2, e));
        q[0][3] = fminf(q[0][3], fmaf(dc3, dc3, e));
        dr = rs1 - pr; e = dr * dr;
        q[1][0] = fminf(q[1][0], fmaf(dc0, dc0, e));
        q[1][1] = fminf(q[1][1], fmaf(dc1, dc1, e));
        q[1][2] = fminf(q[1][2], fmaf(dc2, dc2, e));
        q[1][3] = fminf(q[1][3], fmaf(dc3, dc3, e));
        dr = rs2 - pr; e = dr * dr;
        q[2][0] = fminf(q[2][0], fmaf(dc0, dc0, e));
        q[2][1] = fminf(q[2][1], fmaf(dc1, dc1, e));
        q[2][2] = fminf(q[2][2], fmaf(dc2, dc2, e));
        q[2][3] = fminf(q[2][3], fmaf(dc3, dc3, e));
        dr = rs3 - pr; e = dr * dr;
        q[3][0] = fminf(q[3][0], fmaf(dc0, dc0, e));
        q[3][1] = fminf(q[3][1], fmaf(dc1, dc1, e));
        q[3][2] = fminf(q[3][2], fmaf(dc2, dc2, e));
        q[3][3] = fminf(q[3][3], fmaf(dc3, dc3, e));
    }

    // Single vote for the whole window; active path is fully branchless.
    float wmin = CULL_D2;
#pragma unroll
    for (int i = 0; i < 4; ++i)
#pragma unroll
        for (int j = 0; j < 4; ++j) wmin = fminf(wmin, q[i][j]);

    if (__any_sync(0xffffffffu, wmin < CULL_D2)) {
#pragma unroll
        for (int i = 0; i < 4; ++i) {
            float4 v;
            v.x = tanh_2sqrt_fast(q[i][0]);
            v.y = tanh_2sqrt_fast(q[i][1]);
            v.z = tanh_2sqrt_fast(q[i][2]);
            v.w = tanh_2sqrt_fast(q[i][3]);
            *reinterpret_cast<float4*>(obase + i * W) = v;
        }
    } else {
        const float4 ones = make_float4(1.0f, 1.0f, 1.0f, 1.0f);
#pragma unroll
        for (int i = 0; i < 4; ++i)
            *reinterpret_cast<float4*>(obase + i * W) = ones;
    }
}

}  // namespace

extern "C" void kernel_launch(void* const* d_in, const int* in_sizes, int n_in,
                              void* d_out, int out_size) {
    // d_in[0]: x [B,3,512,512] f32 (unused), d_in[1]: coords [B,48,3] f32
    const float* coords = (const float*)d_in[1];
    float* out = (float*)d_out;

    const int B = in_sizes[1] / (48 * 3);   // 8
    dim3 grid(64, B * 2);                   // 64 blocks x 16 groups, 8 warps each
    distmaps_kernel<<<grid, 256>>>(coords, out);
}

// round 12
// speedup vs baseline: 1.0257x; 1.0257x over previous
#include <cuda_runtime.h>

// DistMaps: out[b,g,r,c] = tanh(2*sqrt(min_p d2)) over 24 clicks per (b,g) group,
// d2 = ((r-pr)/5)^2 + ((c-pc)/5)^2, invalid clicks (max coords < 0) -> 1e6.
// x input (d_in[0]) is shape-only; output depends only on coords (d_in[1]).
//
// R12: R11 falsified the issue-count theory (2x fewer instructions, same 7us).
// The one shared element of all ~7us variants is the per-thread STG.128 store
// path (1M stores, front-batched 4-deep -> cross-CTA L1tex-queue contention
// per the B300 spread model). This round: each CTA computes a 16x512 tile into
// 32KB smem, then ONE cp.async.bulk (TMA store) moves the contiguous tile to
// gmem — 512 bulk stores chip-wide instead of 1M STGs; same bytes, different
// (async-proxy) path.
//
// Tolerance cull retained: writing 1.0f wherever min d2 >= 6.25 gives error
// 1-tanh(5) = 9.1e-5, 10x inside the 1e-3 harness tolerance; interior pixels
// are computed exactly (measured rel_err 4.2e-5 in R11).

namespace {

constexpr int   W         = 512;
constexpr int   P         = 24;      // clicks per group
constexpr int   TR        = 16;      // tile rows per CTA
constexpr float INV_SCALE = 0.2f;    // 1 / (NORM_RADIUS * SPATIAL_SCALE)
constexpr float CULL_D2   = 6.25f;   // 1 - tanh(2*sqrt(6.25)) = 9.1e-5

__device__ __forceinline__ float tanh_2sqrt_fast(float q) {
    float s, t;
    asm("sqrt.approx.f32 %0, %1;" : "=f"(s) : "f"(q));
    s = 2.0f * s;
    asm("tanh.approx.f32 %0, %1;" : "=f"(t) : "f"(s));
    return t;
}

__global__ __launch_bounds__(256, 4) void distmaps_kernel(
    const float* __restrict__ coords,   // [B, 48, 3] (row, col, _)
    float*       __restrict__ out)      // [B, 2, H, W]
{
    __shared__ float s_tile[TR * W];    // 32 KB, contiguous 16x512 tile

    const int tid  = threadIdx.x;
    const int lane = tid & 31;
    const int wid  = tid >> 5;           // 0..7
    const int bg   = blockIdx.y;         // 0..2B-1
    const int tr0  = blockIdx.x << 4;    // tile base row (16 rows)

    // Each warp handles two 4x128 windows of the tile.
#pragma unroll
    for (int k = 0; k < 2; ++k) {
        const int win = (wid << 1) | k;          // 0..15
        const int rb  = (win >> 2) << 2;         // row offset in tile (0,4,8,12)
        const int c0  = (win & 3) << 7;          // col base (0,128,256,384)
        const int r0  = tr0 + rb;                // global row base

        // Lane p tests click p against this 4x128 window.
        float prs = 0.0f, pcs = 0.0f;
        bool  nearp = false;
        if (lane < P) {
            const float* cp = coords + (bg * P + lane) * 3;
            const float pr = __ldg(cp);
            const float pc = __ldg(cp + 1);
            const bool valid = fmaxf(pr, pc) >= 0.0f;   // invalid iff both < 0
            const float rr = fminf(fmaxf(pr, (float)r0), (float)(r0 + 3));
            const float cc = fminf(fmaxf(pc, (float)c0), (float)(c0 + 127));
            const float dr = (rr - pr) * INV_SCALE;
            const float dc = (cc - pc) * INV_SCALE;
            nearp = valid && (fmaf(dr, dr, dc * dc) < CULL_D2);
            prs = pr * INV_SCALE;
            pcs = pc * INV_SCALE;
        }
        unsigned mask = __ballot_sync(0xffffffffu, nearp);

        float* sbase = s_tile + (rb << 9) + (c0 | (lane << 2));

        if (mask == 0u) {
            const float4 ones = make_float4(1.0f, 1.0f, 1.0f, 1.0f);
#pragma unroll
            for (int i = 0; i < 4; ++i)
                *reinterpret_cast<float4*>(sbase + i * W) = ones;
            continue;
        }

        const float a0  = (float)(c0 | (lane << 2)) * INV_SCALE;
        const float a1  = a0 + INV_SCALE;
        const float a2  = a1 + INV_SCALE;
        const float a3  = a2 + INV_SCALE;
        const float rs0 = (float)r0 * INV_SCALE;
        const float rs1 = rs0 + INV_SCALE;
        const float rs2 = rs1 + INV_SCALE;
        const float rs3 = rs2 + INV_SCALE;

        float q[4][4];
#pragma unroll
        for (int i = 0; i < 4; ++i)
#pragma unroll
            for (int j = 0; j < 4; ++j) q[i][j] = CULL_D2;

        while (mask) {
            const int p = __ffs(mask) - 1;
            mask &= mask - 1;
            const float pr = __shfl_sync(0xffffffffu, prs, p);
            const float pc = __shfl_sync(0xffffffffu, pcs, p);

            const float dc0 = a0 - pc, dc1 = a1 - pc, dc2 = a2 - pc, dc3 = a3 - pc;
            float dr, e;
            dr = rs0 - pr; e = dr * dr;
            q[0][0] = fminf(q[0][0], fmaf(dc0, dc0, e));
            q[0][1] = fminf(q[0][1], fmaf(dc1, dc1, e));
            q[0][2] = fminf(q[0][2], fmaf(dc2, dc2, e));
            q[0][3] = fminf(q[0][3], fmaf(dc3, dc3, e));
            dr = rs1 - pr; e = dr * dr;
            q[1][0] = fminf(q[1][0], fmaf(dc0, dc0, e));
            q[1][1] = fminf(q[1][1], fmaf(dc1, dc1, e));
            q[1][2] = fminf(q[1][2], fmaf(dc2, dc2, e));
            q[1][3] = fminf(q[1][3], fmaf(dc3, dc3, e));
            dr = rs2 - pr; e = dr * dr;
            q[2][0] = fminf(q[2][0], fmaf(dc0, dc0, e));
            q[2][1] = fminf(q[2][1], fmaf(dc1, dc1, e));
            q[2][2] = fminf(q[2][2], fmaf(dc2, dc2, e));
            q[2][3] = fminf(q[2][3], fmaf(dc3, dc3, e));
            dr = rs3 - pr; e = dr * dr;
            q[3][0] = fminf(q[3][0], fmaf(dc0, dc0, e));
            q[3][1] = fminf(q[3][1], fmaf(dc1, dc1, e));
            q[3][2] = fminf(q[3][2], fmaf(dc2, dc2, e));
            q[3][3] = fminf(q[3][3], fmaf(dc3, dc3, e));
        }

        float wmin = CULL_D2;
#pragma unroll
        for (int i = 0; i < 4; ++i)
#pragma unroll
            for (int j = 0; j < 4; ++j) wmin = fminf(wmin, q[i][j]);

        if (__any_sync(0xffffffffu, wmin < CULL_D2)) {
#pragma unroll
            for (int i = 0; i < 4; ++i) {
                float4 v;
                v.x = tanh_2sqrt_fast(q[i][0]);
                v.y = tanh_2sqrt_fast(q[i][1]);
                v.z = tanh_2sqrt_fast(q[i][2]);
                v.w = tanh_2sqrt_fast(q[i][3]);
                *reinterpret_cast<float4*>(sbase + i * W) = v;
            }
        } else {
            const float4 ones = make_float4(1.0f, 1.0f, 1.0f, 1.0f);
#pragma unroll
            for (int i = 0; i < 4; ++i)
                *reinterpret_cast<float4*>(sbase + i * W) = ones;
        }
    }

    __syncthreads();

    // One bulk TMA store: contiguous 32KB tile smem -> gmem.
    if (tid == 0) {
        unsigned saddr;
        asm("{ .reg .u64 t; cvta.to.shared.u64 t, %1; cvt.u32.u64 %0, t; }"
            : "=r"(saddr) : "l"(s_tile));
        float* gdst = out + (((unsigned)bg << 18) | ((unsigned)tr0 << 9));
        asm volatile("fence.proxy.async.shared::cta;" ::: "memory");
        asm volatile(
            "cp.async.bulk.global.shared::cta.bulk_group [%0], [%1], %2;"
            :: "l"(gdst), "r"(saddr), "r"((unsigned)(TR * W * 4)) : "memory");
        asm volatile("cp.async.bulk.commit_group;" ::: "memory");
        asm volatile("cp.async.bulk.wait_group 0;" ::: "memory");
    }
}

}  // namespace

extern "C" void kernel_launch(void* const* d_in, const int* in_sizes, int n_in,
                              void* d_out, int out_size) {
    // d_in[0]: x [B,3,512,512] f32 (unused), d_in[1]: coords [B,48,3] f32
    const float* coords = (const float*)d_in[1];
    float* out = (float*)d_out;

    const int B = in_sizes[1] / (48 * 3);   // 8
    dim3 grid(512 / TR, B * 2);             // 32 tiles x 16 groups = 512 CTAs
    distmaps_kernel<<<grid, 256>>>(coords, out);
}

// round 13
// speedup vs baseline: 1.0333x; 1.0074x over previous
#include <cuda_runtime.h>

// DistMaps: out[b,g,r,c] = tanh(2*sqrt(min_p d2)) over 24 clicks per (b,g) group,
// d2 = ((r-pr)/5)^2 + ((c-pc)/5)^2, invalid clicks (max coords < 0) -> 1e6.
// x input (d_in[0]) is shape-only; output depends only on coords (d_in[1]).
//
// R13: every throughput theory is falsified (duration invariant to instrs,
// warps, CTAs, occupancy, and store path). Remaining model term: wave count +
// tail. At regs=40 only ~3.5 CTAs/SM fit -> 1024-CTA grid needs 2+ waves
// (wave transition ~2360 cyc + active-warp tail imbalance). This round forces
// ONE wave: __launch_bounds__(256, 8) (regs <= 32; 8 CTA/SM * 148 = 1184 >=
// 1024), live-set diet (incremental dr/dc instead of rs1..rs3 / a1..a3),
// vote-free branchless epilogue in active warps.
//
// Tolerance cull: writing 1.0f wherever min d2 >= 6.25 errs by 1-tanh(5) =
// 9.1e-5, 10x inside the 1e-3 harness tolerance (measured rel_err 4.2e-5).

namespace {

constexpr int   W         = 512;
constexpr int   P         = 24;      // clicks per group
constexpr float INV_SCALE = 0.2f;    // 1 / (NORM_RADIUS * SPATIAL_SCALE)
constexpr float CULL_D2   = 6.25f;   // 1 - tanh(2*sqrt(6.25)) = 9.1e-5

__device__ __forceinline__ float tanh_2sqrt_fast(float q) {
    float s, t;
    asm("sqrt.approx.f32 %0, %1;" : "=f"(s) : "f"(q));
    s = 2.0f * s;
    asm("tanh.approx.f32 %0, %1;" : "=f"(t) : "f"(s));
    return t;
}

__global__ __launch_bounds__(256, 8) void distmaps_kernel(
    const float* __restrict__ coords,   // [B, 48, 3] (row, col, _)
    float*       __restrict__ out)      // [B, 2, H, W]
{
    const int tid  = threadIdx.x;
    const int lane = tid & 31;
    const int bg   = blockIdx.y;                      // 0..2B-1

    const int wloc = (blockIdx.x << 3) + (tid >> 5);  // 0..511 window in group
    const int r0   = (wloc >> 2) << 2;                // window row base (4 rows)
    const int c0   = (wloc & 3) << 7;                 // window col base (128)

    // Lane p holds click p; test click against this warp's 4x128 window.
    float prs = 0.0f, pcs = 0.0f;
    bool  nearp = false;
    if (lane < P) {
        const float* cp = coords + (bg * P + lane) * 3;
        const float pr = __ldg(cp);
        const float pc = __ldg(cp + 1);
        const bool valid = fmaxf(pr, pc) >= 0.0f;     // invalid iff both < 0
        const float rr = fminf(fmaxf(pr, (float)r0), (float)(r0 + 3));
        const float cc = fminf(fmaxf(pc, (float)c0), (float)(c0 + 127));
        const float dr = (rr - pr) * INV_SCALE;
        const float dc = (cc - pc) * INV_SCALE;
        nearp = valid && (fmaf(dr, dr, dc * dc) < CULL_D2);
        prs = pr * INV_SCALE;
        pcs = pc * INV_SCALE;
    }
    unsigned mask = __ballot_sync(0xffffffffu, nearp);

    // Output index: bg<<18 | r0<<9 | c0 | lane<<2 (disjoint bit fields).
    const unsigned idx = ((unsigned)bg << 18) | ((unsigned)r0 << 9) |
                         (unsigned)(c0 | (lane << 2));
    float* obase = out + idx;

    if (mask == 0u) {
        // No click within reach: all pixels -> 1.0f (err <= 9.1e-5).
        const float4 ones = make_float4(1.0f, 1.0f, 1.0f, 1.0f);
#pragma unroll
        for (int i = 0; i < 4; ++i)
            *reinterpret_cast<float4*>(obase + i * W) = ones;
        return;
    }

    const float a0  = (float)(c0 | (lane << 2)) * INV_SCALE;
    const float rs0 = (float)r0 * INV_SCALE;

    float q[4][4];
#pragma unroll
    for (int i = 0; i < 4; ++i)
#pragma unroll
        for (int j = 0; j < 4; ++j) q[i][j] = CULL_D2;

    // Iterate surviving clicks (warp-uniform mask -> no divergence).
    while (mask) {
        const int p = __ffs(mask) - 1;
        mask &= mask - 1;
        const float pr = __shfl_sync(0xffffffffu, prs, p);
        const float pc = __shfl_sync(0xffffffffu, pcs, p);

        // Incremental column/row deltas keep the live set small (reg cap 32).
        const float dc0 = a0 - pc;
        const float dc1 = dc0 + INV_SCALE;
        const float dc2 = dc1 + INV_SCALE;
        const float dc3 = dc2 + INV_SCALE;
        float dr = rs0 - pr;
#pragma unroll
        for (int i = 0; i < 4; ++i) {
            const float e = dr * dr;
            q[i][0] = fminf(q[i][0], fmaf(dc0, dc0, e));
            q[i][1] = fminf(q[i][1], fmaf(dc1, dc1, e));
            q[i][2] = fminf(q[i][2], fmaf(dc2, dc2, e));
            q[i][3] = fminf(q[i][3], fmaf(dc3, dc3, e));
            dr += INV_SCALE;
        }
    }

    // Branchless epilogue (no vote): active warps always run MUFU.
#pragma unroll
    for (int i = 0; i < 4; ++i) {
        float4 v;
        v.x = tanh_2sqrt_fast(q[i][0]);
        v.y = tanh_2sqrt_fast(q[i][1]);
        v.z = tanh_2sqrt_fast(q[i][2]);
        v.w = tanh_2sqrt_fast(q[i][3]);
        *reinterpret_cast<float4*>(obase + i * W) = v;
    }
}

}  // namespace

extern "C" void kernel_launch(void* const* d_in, const int* in_sizes, int n_in,
                              void* d_out, int out_size) {
    // d_in[0]: x [B,3,512,512] f32 (unused), d_in[1]: coords [B,48,3] f32
    const float* coords = (const float*)d_in[1];
    float* out = (float*)d_out;

    const int B = in_sizes[1] / (48 * 3);   // 8
    dim3 grid(64, B * 2);                   // 1024 CTAs -> single wave @ 8/SM
    distmaps_kernel<<<grid, 256>>>(coords, out);
}